// round 2
// baseline (speedup 1.0000x reference)
#include <cuda_runtime.h>
#include <cuda_bf16.h>
#include <math.h>

#define BB    64
#define NN    4096
#define DD    256
#define KK    11
#define HH    512
#define NITER 5
#define EPSF     1e-8f
#define LN_EPSF  1e-5f
#define SCALEF   0.0625f
#define SPLITN   8
#define TOKB   (NN/SPLITN)   /* 512 tokens per block */
#define TOKW   (TOKB/8)      /* 64 tokens per warp  */
#define SLOTSZ (BB*KK*DD)

// ------------------------- static device scratch -------------------------
__device__ __align__(16) float g_Mqk [DD*DD];
__device__ __align__(16) float g_WvT [DD*DD];
__device__ __align__(16) float g_WihT[DD*3*DD];
__device__ __align__(16) float g_WhhT[DD*3*DD];
__device__ __align__(16) float g_W1T [DD*HH];
__device__ __align__(16) float g_W2T [HH*DD];
__device__ __align__(16) float g_slots[SLOTSZ];
__device__ __align__(16) float g_mid  [SLOTSZ];   // updates, later LN_p(slots)
__device__ __align__(16) float g_qt   [SLOTSZ];
__device__ __align__(16) float g_qbias[BB*KK];
__device__ __align__(16) float g_h1 [BB*KK*HH];
__device__ __align__(16) float g_pU [(size_t)BB*SPLITN*KK*DD];
__device__ __align__(16) float g_pS [BB*SPLITN*16];
__device__ __align__(16) float g_pg [(size_t)BB*4*KK*6*DD];   // GRU e-split partials
__device__ __align__(16) float g_pm [(size_t)BB*2*KK*DD];     // MLP2 e-split partials

// ------------------------- helpers -------------------------
__device__ __forceinline__ float blockSum(float v, float* red) {
    // blockDim.x == 256 in all callers
    #pragma unroll
    for (int o = 16; o; o >>= 1) v += __shfl_xor_sync(0xffffffffu, v, o);
    int lane = threadIdx.x & 31, wid = threadIdx.x >> 5;
    __syncthreads();
    if (lane == 0) red[wid] = v;
    __syncthreads();
    float t = 0.f;
    #pragma unroll
    for (int w = 0; w < 8; w++) t += red[w];
    return t;
}

__device__ __forceinline__ float sigm(float x) { return 1.f / (1.f + __expf(-x)); }

// ------------------------- weight prep -------------------------
__global__ void k_transpose(const float* __restrict__ src, int R, int C, int which) {
    __shared__ float tile[32][33];
    float* dst = (which == 0) ? g_WvT : (which == 1) ? g_WihT :
                 (which == 2) ? g_WhhT : (which == 3) ? g_W1T : g_W2T;
    int bx = blockIdx.x * 32, by = blockIdx.y * 32;
    int x = bx + threadIdx.x;
    #pragma unroll
    for (int yy = 0; yy < 32; yy += 8) {
        int y = by + threadIdx.y + yy;
        if (y < R && x < C) tile[threadIdx.y + yy][threadIdx.x] = src[(size_t)y * C + x];
    }
    __syncthreads();
    int x2 = by + threadIdx.x;              // row index of src (runs over R? no: over the by range)
    #pragma unroll
    for (int yy = 0; yy < 32; yy += 8) {
        int y2 = bx + threadIdx.y + yy;     // col index of src
        if (y2 < C && x2 < R) dst[(size_t)y2 * R + x2] = tile[threadIdx.x][threadIdx.y + yy];
    }
}

// Mqk[e][f] = sum_d Wq[d][e]*Wk[d][f] * SCALE
__global__ void k_mqk(const float* __restrict__ Wq, const float* __restrict__ Wk) {
    int e = blockIdx.x, f = threadIdx.x;
    float acc = 0.f;
    for (int d = 0; d < DD; d++)
        acc = fmaf(Wq[d * DD + e], Wk[d * DD + f], acc);
    g_Mqk[e * DD + f] = acc * SCALEF;
}

__global__ void k_copy_slots(const float* __restrict__ src) {
    int i = blockIdx.x * 256 + threadIdx.x;
    if (i < SLOTSZ) g_slots[i] = src[i];
}

// ------------------------- per-iter: q~ = LN_s(slots) @ Mqk, plus qbias -------------------------
__global__ void k_qgen(const float* __restrict__ lsw, const float* __restrict__ lsb,
                       const float* __restrict__ lfb) {
    __shared__ float sQ[KK][DD];
    __shared__ float red[32];
    int b = blockIdx.x, t = threadIdx.x;
    for (int r = 0; r < KK; r++) {
        float v = g_slots[(b * KK + r) * DD + t];
        float m = blockSum(v, red) * (1.f / DD);
        float d = v - m;
        float var = blockSum(d * d, red) * (1.f / DD);
        sQ[r][t] = d * rsqrtf(var + LN_EPSF) * lsw[t] + lsb[t];
    }
    __syncthreads();
    float acc[KK];
    #pragma unroll
    for (int r = 0; r < KK; r++) acc[r] = 0.f;
    for (int e = 0; e < DD; e++) {
        float mv = g_Mqk[e * DD + t];
        #pragma unroll
        for (int r = 0; r < KK; r++) acc[r] = fmaf(sQ[r][e], mv, acc[r]);
    }
    #pragma unroll
    for (int r = 0; r < KK; r++) g_qt[(b * KK + r) * DD + t] = acc[r];
    float bt = lfb[t];
    for (int r = 0; r < KK; r++) {
        float qb = blockSum(acc[r] * bt, red);
        if (t == 0) g_qbias[b * KK + r] = qb;
    }
}

// ------------------------- per-iter: streaming attention -------------------------
__global__ void __launch_bounds__(256, 1) k_attn(const float* __restrict__ inp,
                                                 const float* __restrict__ lfw) {
    __shared__ float sCopy[4][KK * DD];   // 45056 B
    __shared__ float sS[8][16];
    int b = blockIdx.x, sp = blockIdx.y;
    int tid = threadIdx.x, w = tid >> 5, l = tid & 31;

    // q~ with ln_f_w folded in; lane owns dims [8l, 8l+8)
    float4 qa[KK], qb[KK];
    {
        const float4* wv4 = (const float4*)lfw;
        float4 w0 = wv4[2 * l], w1 = wv4[2 * l + 1];
        const float4* qp = (const float4*)(g_qt + (size_t)b * KK * DD);
        #pragma unroll
        for (int i = 0; i < KK; i++) {
            float4 a = qp[i * 64 + 2 * l], c = qp[i * 64 + 2 * l + 1];
            a.x *= w0.x; a.y *= w0.y; a.z *= w0.z; a.w *= w0.w;
            c.x *= w1.x; c.y *= w1.y; c.z *= w1.z; c.w *= w1.w;
            qa[i] = a; qb[i] = c;
        }
    }
    float qbias[KK];
    #pragma unroll
    for (int i = 0; i < KK; i++) qbias[i] = g_qbias[b * KK + i];

    float Ua[KK][8];
    float Sacc[KK];
    #pragma unroll
    for (int i = 0; i < KK; i++) {
        Sacc[i] = 0.f;
        #pragma unroll
        for (int k = 0; k < 8; k++) Ua[i][k] = 0.f;
    }

    int j0 = sp * TOKB + w * TOKW;
    const float4* xrow = (const float4*)(inp + ((size_t)b * NN + j0) * DD);

    float4 xa = xrow[2 * l], xb = xrow[2 * l + 1];
    for (int tt = 0; tt < TOKW; tt++) {
        int nt = (tt + 1 < TOKW) ? tt + 1 : tt;
        float4 na = xrow[nt * 64 + 2 * l];
        float4 nb = xrow[nt * 64 + 2 * l + 1];

        // LayerNorm stats across the warp (token row = 256 floats)
        float s = xa.x + xa.y + xa.z + xa.w + xb.x + xb.y + xb.z + xb.w;
        #pragma unroll
        for (int o = 16; o; o >>= 1) s += __shfl_xor_sync(0xffffffffu, s, o);
        float m = s * (1.f / DD);
        float c[8];
        c[0] = xa.x - m; c[1] = xa.y - m; c[2] = xa.z - m; c[3] = xa.w - m;
        c[4] = xb.x - m; c[5] = xb.y - m; c[6] = xb.z - m; c[7] = xb.w - m;
        float vs = 0.f;
        #pragma unroll
        for (int k = 0; k < 8; k++) vs = fmaf(c[k], c[k], vs);
        #pragma unroll
        for (int o = 16; o; o >>= 1) vs += __shfl_xor_sync(0xffffffffu, vs, o);
        float rs = rsqrtf(vs * (1.f / DD) + LN_EPSF);
        float nh[8];
        #pragma unroll
        for (int k = 0; k < 8; k++) nh[k] = c[k] * rs;   // pre-affine normalized

        // dots for 11 slots
        float p[KK];
        #pragma unroll
        for (int i = 0; i < KK; i++) {
            float a = qa[i].x * nh[0];
            a = fmaf(qa[i].y, nh[1], a);
            a = fmaf(qa[i].z, nh[2], a);
            a = fmaf(qa[i].w, nh[3], a);
            a = fmaf(qb[i].x, nh[4], a);
            a = fmaf(qb[i].y, nh[5], a);
            a = fmaf(qb[i].z, nh[6], a);
            a = fmaf(qb[i].w, nh[7], a);
            p[i] = a;
        }
        #pragma unroll
        for (int o = 16; o; o >>= 1) {
            #pragma unroll
            for (int i = 0; i < KK; i++) p[i] += __shfl_xor_sync(0xffffffffu, p[i], o);
        }
        // softmax over 11 slots (per token), + EPS
        float mx = p[0] + qbias[0];
        #pragma unroll
        for (int i = 0; i < KK; i++) { p[i] += qbias[i]; mx = fmaxf(mx, p[i]); }
        float se = 0.f;
        #pragma unroll
        for (int i = 0; i < KK; i++) { p[i] = __expf(p[i] - mx); se += p[i]; }
        float inv = 1.f / se;
        #pragma unroll
        for (int i = 0; i < KK; i++) {
            float a = fmaf(p[i], inv, EPSF);
            Sacc[i] += a;
            #pragma unroll
            for (int k = 0; k < 8; k++) Ua[i][k] = fmaf(a, nh[k], Ua[i][k]);
        }
        xa = na; xb = nb;
    }

    // block combine: 4 copies, no atomics
    {
        float* myc = sCopy[w & 3];
        if (w < 4) {
            #pragma unroll
            for (int i = 0; i < KK; i++) {
                *(float4*)&myc[i * DD + 8 * l]     = make_float4(Ua[i][0], Ua[i][1], Ua[i][2], Ua[i][3]);
                *(float4*)&myc[i * DD + 8 * l + 4] = make_float4(Ua[i][4], Ua[i][5], Ua[i][6], Ua[i][7]);
            }
        }
        __syncthreads();
        if (w >= 4) {
            #pragma unroll
            for (int i = 0; i < KK; i++) {
                float4 a = *(float4*)&myc[i * DD + 8 * l];
                float4 bq = *(float4*)&myc[i * DD + 8 * l + 4];
                a.x += Ua[i][0]; a.y += Ua[i][1]; a.z += Ua[i][2]; a.w += Ua[i][3];
                bq.x += Ua[i][4]; bq.y += Ua[i][5]; bq.z += Ua[i][6]; bq.w += Ua[i][7];
                *(float4*)&myc[i * DD + 8 * l]     = a;
                *(float4*)&myc[i * DD + 8 * l + 4] = bq;
            }
        }
        if (l == 0) {
            #pragma unroll
            for (int i = 0; i < KK; i++) sS[w][i] = Sacc[i];
        }
        __syncthreads();
        float* outp = g_pU + ((size_t)(b * SPLITN + sp)) * (KK * DD);
        for (int idx = tid; idx < KK * DD; idx += 256)
            outp[idx] = sCopy[0][idx] + sCopy[1][idx] + sCopy[2][idx] + sCopy[3][idx];
        if (tid < KK) {
            float ss = 0.f;
            #pragma unroll
            for (int ww = 0; ww < 8; ww++) ss += sS[ww][tid];
            g_pS[(b * SPLITN + sp) * 16 + tid] = ss;
        }
    }
}

// ------------------------- per-iter: combine partials + Wv^T -> updates -------------------------
__global__ void k_comb(const float* __restrict__ lfw, const float* __restrict__ lfb) {
    __shared__ float sUn[KK][DD];
    __shared__ float sSv[KK];
    int b = blockIdx.x, t = threadIdx.x;
    if (t < KK) {
        float s = 0.f;
        for (int sp = 0; sp < SPLITN; sp++) s += g_pS[(b * SPLITN + sp) * 16 + t];
        sSv[t] = s;
    }
    __syncthreads();
    float wt = lfw[t], bt = lfb[t];
    for (int i = 0; i < KK; i++) {
        float u = 0.f;
        for (int sp = 0; sp < SPLITN; sp++)
            u += g_pU[((size_t)(b * SPLITN + sp)) * (KK * DD) + i * DD + t];
        // Un = (w*Uhat + b*S)/S = w*Uhat/S + b  (re-apply LN affine analytically)
        sUn[i][t] = fmaf(wt, u / sSv[i], bt);
    }
    __syncthreads();
    float acc[KK];
    #pragma unroll
    for (int i = 0; i < KK; i++) acc[i] = 0.f;
    for (int e = 0; e < DD; e++) {
        float wv = g_WvT[e * DD + t];
        #pragma unroll
        for (int i = 0; i < KK; i++) acc[i] = fmaf(sUn[i][e], wv, acc[i]);
    }
    #pragma unroll
    for (int i = 0; i < KK; i++) g_mid[(b * KK + i) * DD + t] = acc[i];
}

// ------------------------- per-iter: GRU (e-split partials) -------------------------
__global__ void k_gru1() {
    __shared__ float sU[KK][DD];
    __shared__ float sH[KK][DD];
    int b = blockIdx.x, eq = blockIdx.y, t = threadIdx.x;
    for (int r = 0; r < KK; r++) {
        sU[r][t] = g_mid[(b * KK + r) * DD + t];
        sH[r][t] = g_slots[(b * KK + r) * DD + t];
    }
    __syncthreads();
    float air[KK], aiz[KK], ain[KK], ahr[KK], ahz[KK], ahn[KK];
    #pragma unroll
    for (int r = 0; r < KK; r++) { air[r]=aiz[r]=ain[r]=ahr[r]=ahz[r]=ahn[r]=0.f; }
    int e0 = eq * (DD / 4);
    for (int ee = 0; ee < DD / 4; ee++) {
        int e = e0 + ee;
        float wir = g_WihT[e * (3*DD) + t];
        float wiz = g_WihT[e * (3*DD) + DD + t];
        float win = g_WihT[e * (3*DD) + 2*DD + t];
        float whr = g_WhhT[e * (3*DD) + t];
        float whz = g_WhhT[e * (3*DD) + DD + t];
        float whn = g_WhhT[e * (3*DD) + 2*DD + t];
        #pragma unroll
        for (int r = 0; r < KK; r++) {
            float u = sU[r][e], h = sH[r][e];
            air[r] = fmaf(u, wir, air[r]);
            aiz[r] = fmaf(u, wiz, aiz[r]);
            ain[r] = fmaf(u, win, ain[r]);
            ahr[r] = fmaf(h, whr, ahr[r]);
            ahz[r] = fmaf(h, whz, ahz[r]);
            ahn[r] = fmaf(h, whn, ahn[r]);
        }
    }
    float* o = g_pg + ((size_t)(b * 4 + eq) * KK) * (6 * DD);
    for (int r = 0; r < KK; r++) {
        o[r * 6*DD + 0*DD + t] = air[r];
        o[r * 6*DD + 1*DD + t] = aiz[r];
        o[r * 6*DD + 2*DD + t] = ain[r];
        o[r * 6*DD + 3*DD + t] = ahr[r];
        o[r * 6*DD + 4*DD + t] = ahz[r];
        o[r * 6*DD + 5*DD + t] = ahn[r];
    }
}

__global__ void k_gru2(const float* __restrict__ bih, const float* __restrict__ bhh,
                       const float* __restrict__ lpw, const float* __restrict__ lpb) {
    __shared__ float red[32];
    int b = blockIdx.x, t = threadIdx.x;
    for (int r = 0; r < KK; r++) {
        float ir = bih[t], iz = bih[DD + t], in_ = bih[2*DD + t];
        float hr = bhh[t], hz = bhh[DD + t], hn = bhh[2*DD + t];
        for (int eq = 0; eq < 4; eq++) {
            const float* p = g_pg + ((size_t)(b * 4 + eq) * KK + r) * (6 * DD);
            ir += p[t]; iz += p[DD + t]; in_ += p[2*DD + t];
            hr += p[3*DD + t]; hz += p[4*DD + t]; hn += p[5*DD + t];
        }
        float rg = sigm(ir + hr);
        float z  = sigm(iz + hz);
        float n  = tanhf(fmaf(rg, hn, in_));
        float hprev = g_slots[(b * KK + r) * DD + t];
        float hy = fmaf(z, hprev - n, n);   // (1-z)*n + z*hprev
        // LN_p
        float m  = blockSum(hy, red) * (1.f / DD);
        float d  = hy - m;
        float var = blockSum(d * d, red) * (1.f / DD);
        float lnp = d * rsqrtf(var + LN_EPSF) * lpw[t] + lpb[t];
        g_slots[(b * KK + r) * DD + t] = hy;
        g_mid  [(b * KK + r) * DD + t] = lnp;
    }
}

// ------------------------- per-iter: MLP -------------------------
__global__ void k_mlp1(const float* __restrict__ b1) {
    __shared__ float sP[KK][DD];
    int b = blockIdx.x, q = blockIdx.y, t = threadIdx.x;
    int h = q * DD + t;
    for (int r = 0; r < KK; r++) sP[r][t] = g_mid[(b * KK + r) * DD + t];
    __syncthreads();
    float acc[KK];
    #pragma unroll
    for (int r = 0; r < KK; r++) acc[r] = 0.f;
    for (int e = 0; e < DD; e++) {
        float wv = g_W1T[e * HH + h];
        #pragma unroll
        for (int r = 0; r < KK; r++) acc[r] = fmaf(sP[r][e], wv, acc[r]);
    }
    float bb = b1[h];
    #pragma unroll
    for (int r = 0; r < KK; r++)
        g_h1[(b * KK + r) * HH + h] = fmaxf(acc[r] + bb, 0.f);
}

__global__ void k_mlp2() {
    __shared__ float sh1[KK][DD];
    int b = blockIdx.x, eh = blockIdx.y, t = threadIdx.x;
    for (int r = 0; r < KK; r++) sh1[r][t] = g_h1[(b * KK + r) * HH + eh * DD + t];
    __syncthreads();
    float acc[KK];
    #pragma unroll
    for (int r = 0; r < KK; r++) acc[r] = 0.f;
    for (int e = 0; e < DD; e++) {
        float wv = g_W2T[(eh * DD + e) * DD + t];
        #pragma unroll
        for (int r = 0; r < KK; r++) acc[r] = fmaf(sh1[r][e], wv, acc[r]);
    }
    #pragma unroll
    for (int r = 0; r < KK; r++)
        g_pm[((size_t)(b * 2 + eh) * KK + r) * DD + t] = acc[r];
}

__global__ void k_mlp2b(const float* __restrict__ b2, float* __restrict__ outp) {
    int b = blockIdx.x, t = threadIdx.x;
    float bt = b2[t];
    for (int r = 0; r < KK; r++) {
        int idx = (b * KK + r) * DD + t;
        float v = g_slots[idx]
                + g_pm[((size_t)(b * 2 + 0) * KK + r) * DD + t]
                + g_pm[((size_t)(b * 2 + 1) * KK + r) * DD + t]
                + bt;
        g_slots[idx] = v;
        outp[idx] = v;
    }
}

// ------------------------- launch -------------------------
extern "C" void kernel_launch(void* const* d_in, const int* in_sizes, int n_in,
                              void* d_out, int out_size) {
    const float* inputs = (const float*)d_in[0];
    const float* slots0 = (const float*)d_in[1];
    const float* ln_f_w = (const float*)d_in[2];
    const float* ln_f_b = (const float*)d_in[3];
    const float* ln_s_w = (const float*)d_in[4];
    const float* ln_s_b = (const float*)d_in[5];
    const float* ln_p_w = (const float*)d_in[6];
    const float* ln_p_b = (const float*)d_in[7];
    const float* Wq  = (const float*)d_in[8];
    const float* Wk  = (const float*)d_in[9];
    const float* Wv  = (const float*)d_in[10];
    const float* Wih = (const float*)d_in[11];
    const float* bih = (const float*)d_in[12];
    const float* Whh = (const float*)d_in[13];
    const float* bhh = (const float*)d_in[14];
    const float* W1  = (const float*)d_in[15];
    const float* b1  = (const float*)d_in[16];
    const float* W2  = (const float*)d_in[17];
    const float* b2  = (const float*)d_in[18];
    float* outp = (float*)d_out;

    dim3 t32x8(32, 8);
    k_transpose<<<dim3(8, 8),  t32x8>>>(Wv,  DD,   DD, 0);
    k_transpose<<<dim3(8, 24), t32x8>>>(Wih, 3*DD, DD, 1);
    k_transpose<<<dim3(8, 24), t32x8>>>(Whh, 3*DD, DD, 2);
    k_transpose<<<dim3(8, 16), t32x8>>>(W1,  HH,   DD, 3);
    k_transpose<<<dim3(16, 8), t32x8>>>(W2,  DD,   HH, 4);
    k_mqk<<<DD, DD>>>(Wq, Wk);
    k_copy_slots<<<(SLOTSZ + 255) / 256, 256>>>(slots0);

    for (int it = 0; it < NITER; it++) {
        k_qgen<<<BB, DD>>>(ln_s_w, ln_s_b, ln_f_b);
        k_attn<<<dim3(BB, SPLITN), 256>>>(inputs, ln_f_w);
        k_comb<<<BB, DD>>>(ln_f_w, ln_f_b);
        k_gru1<<<dim3(BB, 4), DD>>>();
        k_gru2<<<BB, DD>>>(bih, bhh, ln_p_w, ln_p_b);
        k_mlp1<<<dim3(BB, 2), DD>>>(b1);
        k_mlp2<<<dim3(BB, 2), DD>>>();
        k_mlp2b<<<BB, DD>>>(b2, outp);
    }
}

// round 3
// speedup vs baseline: 1.4857x; 1.4857x over previous
#include <cuda_runtime.h>
#include <cuda_bf16.h>
#include <math.h>

#define BB    64
#define NN    4096
#define DD    256
#define KK    11
#define HH    512
#define NITER 5
#define EPSF     1e-8f
#define LN_EPSF  1e-5f
#define SCALEF   0.0625f
#define SPLITN   16
#define TOKB   (NN/SPLITN)   /* 256 tokens per block */
#define TOKW   (TOKB/4)      /* 64 tokens per warp (4 warps/block) */
#define SLOTSZ (BB*KK*DD)

// ------------------------- static device scratch -------------------------
__device__ __align__(16) float g_xh  [(size_t)BB*NN*DD];   // pre-affine LN(inputs), fp32
__device__ __align__(16) float g_Mqk [DD*DD];
__device__ __align__(16) float g_WvT [DD*DD];
__device__ __align__(16) float g_WihT[DD*3*DD];
__device__ __align__(16) float g_WhhT[DD*3*DD];
__device__ __align__(16) float g_W1T [DD*HH];
__device__ __align__(16) float g_W2T [HH*DD];
__device__ __align__(16) float g_slots[SLOTSZ];
__device__ __align__(16) float g_mid  [SLOTSZ];
__device__ __align__(16) float g_qt   [SLOTSZ];            // (LN_s(slots)@Mqk) ⊙ ln_f_w
__device__ __align__(16) float g_qbias[BB*KK];
__device__ __align__(16) float g_h1 [BB*KK*HH];
__device__ __align__(16) float g_pU [(size_t)BB*SPLITN*KK*DD];
__device__ __align__(16) float g_pS [BB*SPLITN*16];
__device__ __align__(16) float g_pg [(size_t)BB*4*KK*6*DD];
__device__ __align__(16) float g_pm [(size_t)BB*2*KK*DD];

// ------------------------- f32x2 helpers -------------------------
typedef unsigned long long ull;
__device__ __forceinline__ ull pk2(float lo, float hi) {
    ull r; asm("mov.b64 %0, {%1, %2};" : "=l"(r) : "f"(lo), "f"(hi)); return r;
}
__device__ __forceinline__ void upk2(float& lo, float& hi, ull v) {
    asm("mov.b64 {%0, %1}, %2;" : "=f"(lo), "=f"(hi) : "l"(v));
}
__device__ __forceinline__ ull fma2(ull a, ull b, ull c) {
    ull d; asm("fma.rn.f32x2 %0, %1, %2, %3;" : "=l"(d) : "l"(a), "l"(b), "l"(c)); return d;
}
__device__ __forceinline__ ull mul2(ull a, ull b) {
    ull d; asm("mul.rn.f32x2 %0, %1, %2;" : "=l"(d) : "l"(a), "l"(b)); return d;
}

__device__ __forceinline__ float blockSum(float v, float* red) {
    // requires blockDim.x == 256
    #pragma unroll
    for (int o = 16; o; o >>= 1) v += __shfl_xor_sync(0xffffffffu, v, o);
    int lane = threadIdx.x & 31, wid = threadIdx.x >> 5;
    __syncthreads();
    if (lane == 0) red[wid] = v;
    __syncthreads();
    float t = 0.f;
    #pragma unroll
    for (int w = 0; w < 8; w++) t += red[w];
    return t;
}

__device__ __forceinline__ float sigm(float x) { return 1.f / (1.f + __expf(-x)); }

// ------------------------- prep: all 5 transposes in one launch -------------------------
__global__ void k_transAll(const float* __restrict__ Wv,  const float* __restrict__ Wih,
                           const float* __restrict__ Whh, const float* __restrict__ W1,
                           const float* __restrict__ W2) {
    __shared__ float tile[32][33];
    int bid = blockIdx.x;
    const float* src; float* dst; int R, C, tx, t0;
    if (bid < 64)       { src = Wv;  dst = g_WvT;  R = DD;   C = DD; tx = 8;  t0 = 0;   }
    else if (bid < 256) { src = Wih; dst = g_WihT; R = 3*DD; C = DD; tx = 8;  t0 = 64;  }
    else if (bid < 448) { src = Whh; dst = g_WhhT; R = 3*DD; C = DD; tx = 8;  t0 = 256; }
    else if (bid < 576) { src = W1;  dst = g_W1T;  R = HH;   C = DD; tx = 8;  t0 = 448; }
    else                { src = W2;  dst = g_W2T;  R = DD;   C = HH; tx = 16; t0 = 576; }
    int tb = bid - t0;
    int bx = (tb % tx) * 32, by = (tb / tx) * 32;
    int x = bx + threadIdx.x;
    #pragma unroll
    for (int yy = 0; yy < 32; yy += 8) {
        int y = by + threadIdx.y + yy;
        if (y < R && x < C) tile[threadIdx.y + yy][threadIdx.x] = src[(size_t)y * C + x];
    }
    __syncthreads();
    int x2 = by + threadIdx.x;
    #pragma unroll
    for (int yy = 0; yy < 32; yy += 8) {
        int y2 = bx + threadIdx.y + yy;
        if (y2 < C && x2 < R) dst[(size_t)y2 * R + x2] = tile[threadIdx.x][threadIdx.y + yy];
    }
}

// Mqk[e][f] = sum_d Wq[d][e]*Wk[d][f] * SCALE
__global__ void k_mqk(const float* __restrict__ Wq, const float* __restrict__ Wk) {
    int e = blockIdx.x, f = threadIdx.x;
    float acc = 0.f;
    for (int d = 0; d < DD; d++)
        acc = fmaf(Wq[d * DD + e], Wk[d * DD + f], acc);
    g_Mqk[e * DD + f] = acc * SCALEF;
}

__global__ void k_copy_slots(const float* __restrict__ src) {
    int i = blockIdx.x * 256 + threadIdx.x;
    if (i < SLOTSZ) g_slots[i] = src[i];
}

// ------------------------- prep: x_hat = (x - m) * rsqrt(var + eps), pre-affine -------------------------
__global__ void k_xhat(const float* __restrict__ inp) {
    // warp per token; block = 8 tokens
    int l = threadIdx.x & 31, w = threadIdx.x >> 5;
    size_t row = (size_t)blockIdx.x * 8 + w;
    const float4* rp = (const float4*)(inp + row * DD);
    float4 a = rp[2 * l], b = rp[2 * l + 1];
    float s = a.x + a.y + a.z + a.w + b.x + b.y + b.z + b.w;
    #pragma unroll
    for (int o = 16; o; o >>= 1) s += __shfl_xor_sync(0xffffffffu, s, o);
    float m = s * (1.f / DD);
    a.x -= m; a.y -= m; a.z -= m; a.w -= m;
    b.x -= m; b.y -= m; b.z -= m; b.w -= m;
    float vs = a.x*a.x + a.y*a.y + a.z*a.z + a.w*a.w
             + b.x*b.x + b.y*b.y + b.z*b.z + b.w*b.w;
    #pragma unroll
    for (int o = 16; o; o >>= 1) vs += __shfl_xor_sync(0xffffffffu, vs, o);
    float rs = rsqrtf(vs * (1.f / DD) + LN_EPSF);
    a.x *= rs; a.y *= rs; a.z *= rs; a.w *= rs;
    b.x *= rs; b.y *= rs; b.z *= rs; b.w *= rs;
    float4* op = (float4*)(g_xh + row * DD);
    op[2 * l] = a; op[2 * l + 1] = b;
}

// ------------------------- per-iter: q~ = (LN_s(slots)@Mqk) ⊙ w_f, and qbias -------------------------
__global__ void k_qgen(const float* __restrict__ lsw, const float* __restrict__ lsb,
                       const float* __restrict__ lfw, const float* __restrict__ lfb) {
    __shared__ float sQ[KK][DD];
    __shared__ float red[32];
    int b = blockIdx.x, t = threadIdx.x;
    for (int r = 0; r < KK; r++) {
        float v = g_slots[(b * KK + r) * DD + t];
        float m = blockSum(v, red) * (1.f / DD);
        float d = v - m;
        float var = blockSum(d * d, red) * (1.f / DD);
        sQ[r][t] = d * rsqrtf(var + LN_EPSF) * lsw[t] + lsb[t];
    }
    __syncthreads();
    float acc[KK];
    #pragma unroll
    for (int r = 0; r < KK; r++) acc[r] = 0.f;
    for (int e = 0; e < DD; e++) {
        float mv = g_Mqk[e * DD + t];
        #pragma unroll
        for (int r = 0; r < KK; r++) acc[r] = fmaf(sQ[r][e], mv, acc[r]);
    }
    float wt = lfw[t], bt = lfb[t];
    for (int r = 0; r < KK; r++) {
        float qb = blockSum(acc[r] * bt, red);
        if (t == 0) g_qbias[b * KK + r] = qb;
    }
    #pragma unroll
    for (int r = 0; r < KK; r++) g_qt[(b * KK + r) * DD + t] = acc[r] * wt;
}

// ------------------------- per-iter: streaming attention (f32x2) -------------------------
__global__ void __launch_bounds__(128) k_attn() {
    __shared__ float sC[2][KK * DD];      // 22528 B
    __shared__ float sS4[4][16];
    int b = blockIdx.x, sp = blockIdx.y;
    int tid = threadIdx.x, w = tid >> 5, l = tid & 31;

    // q (ln_f_w pre-folded); lane owns dims [8l, 8l+8) as 4 f32x2 pairs
    ull q2[KK][4];
    {
        const float4* qp = (const float4*)(g_qt + (size_t)b * KK * DD);
        #pragma unroll
        for (int i = 0; i < KK; i++) {
            float4 a = qp[i * 64 + 2 * l], c = qp[i * 64 + 2 * l + 1];
            q2[i][0] = pk2(a.x, a.y); q2[i][1] = pk2(a.z, a.w);
            q2[i][2] = pk2(c.x, c.y); q2[i][3] = pk2(c.z, c.w);
        }
    }
    float qb_[KK];
    #pragma unroll
    for (int i = 0; i < KK; i++) qb_[i] = g_qbias[b * KK + i];

    ull U2[KK][4];
    float Sacc[KK];
    #pragma unroll
    for (int i = 0; i < KK; i++) {
        Sacc[i] = 0.f;
        #pragma unroll
        for (int k = 0; k < 4; k++) U2[i][k] = 0ull;
    }

    int j0 = sp * TOKB + w * TOKW;
    const float4* xrow = (const float4*)(g_xh + ((size_t)b * NN + j0) * DD);

    float4 xa = xrow[2 * l], xb = xrow[2 * l + 1];
    for (int tt = 0; tt < TOKW; tt++) {
        int nt = (tt + 1 < TOKW) ? tt + 1 : tt;
        float4 na = xrow[nt * 64 + 2 * l];
        float4 nb = xrow[nt * 64 + 2 * l + 1];

        ull n2[4];
        n2[0] = pk2(xa.x, xa.y); n2[1] = pk2(xa.z, xa.w);
        n2[2] = pk2(xb.x, xb.y); n2[3] = pk2(xb.z, xb.w);

        // dots (f32x2 chains) + pair-collapse
        float p[KK];
        #pragma unroll
        for (int i = 0; i < KK; i++) {
            ull t2 = mul2(q2[i][3], n2[3]);
            t2 = fma2(q2[i][2], n2[2], t2);
            t2 = fma2(q2[i][1], n2[1], t2);
            t2 = fma2(q2[i][0], n2[0], t2);
            float lo, hi; upk2(lo, hi, t2);
            p[i] = lo + hi;
        }
        #pragma unroll
        for (int o = 16; o; o >>= 1) {
            #pragma unroll
            for (int i = 0; i < KK; i++) p[i] += __shfl_xor_sync(0xffffffffu, p[i], o);
        }
        // softmax over slots (+ EPS)
        float mx = p[0] + qb_[0];
        #pragma unroll
        for (int i = 0; i < KK; i++) { p[i] += qb_[i]; mx = fmaxf(mx, p[i]); }
        float se = 0.f;
        #pragma unroll
        for (int i = 0; i < KK; i++) { p[i] = __expf(p[i] - mx); se += p[i]; }
        float inv = 1.f / se;
        #pragma unroll
        for (int i = 0; i < KK; i++) {
            float a = fmaf(p[i], inv, EPSF);
            Sacc[i] += a;
            ull a2 = pk2(a, a);
            U2[i][0] = fma2(a2, n2[0], U2[i][0]);
            U2[i][1] = fma2(a2, n2[1], U2[i][1]);
            U2[i][2] = fma2(a2, n2[2], U2[i][2]);
            U2[i][3] = fma2(a2, n2[3], U2[i][3]);
        }
        xa = na; xb = nb;
    }

    // block combine (4 warps, 2 smem copies, no atomics)
    float* myc = sC[w & 1];
    if (w < 2) {
        #pragma unroll
        for (int i = 0; i < KK; i++) {
            float u0,u1,u2,u3,u4,u5,u6,u7;
            upk2(u0,u1,U2[i][0]); upk2(u2,u3,U2[i][1]);
            upk2(u4,u5,U2[i][2]); upk2(u6,u7,U2[i][3]);
            *(float4*)&myc[i * DD + 8 * l]     = make_float4(u0,u1,u2,u3);
            *(float4*)&myc[i * DD + 8 * l + 4] = make_float4(u4,u5,u6,u7);
        }
    }
    __syncthreads();
    if (w >= 2) {
        #pragma unroll
        for (int i = 0; i < KK; i++) {
            float u0,u1,u2,u3,u4,u5,u6,u7;
            upk2(u0,u1,U2[i][0]); upk2(u2,u3,U2[i][1]);
            upk2(u4,u5,U2[i][2]); upk2(u6,u7,U2[i][3]);
            float4 a = *(float4*)&myc[i * DD + 8 * l];
            float4 c = *(float4*)&myc[i * DD + 8 * l + 4];
            a.x += u0; a.y += u1; a.z += u2; a.w += u3;
            c.x += u4; c.y += u5; c.z += u6; c.w += u7;
            *(float4*)&myc[i * DD + 8 * l]     = a;
            *(float4*)&myc[i * DD + 8 * l + 4] = c;
        }
    }
    if (l == 0) {
        #pragma unroll
        for (int i = 0; i < KK; i++) sS4[w][i] = Sacc[i];
    }
    __syncthreads();
    float* outp = g_pU + ((size_t)(b * SPLITN + sp)) * (KK * DD);
    for (int idx = tid; idx < KK * DD; idx += 128)
        outp[idx] = sC[0][idx] + sC[1][idx];
    if (tid < KK)
        g_pS[(b * SPLITN + sp) * 16 + tid] =
            sS4[0][tid] + sS4[1][tid] + sS4[2][tid] + sS4[3][tid];
}

// ------------------------- per-iter: combine partials + Wv^T -> updates -------------------------
__global__ void k_comb(const float* __restrict__ lfw, const float* __restrict__ lfb) {
    __shared__ float sUn[KK][DD];
    __shared__ float sSv[KK];
    int b = blockIdx.x, t = threadIdx.x;
    if (t < KK) {
        float s = 0.f;
        for (int sp = 0; sp < SPLITN; sp++) s += g_pS[(b * SPLITN + sp) * 16 + t];
        sSv[t] = s;
    }
    __syncthreads();
    float wt = lfw[t], bt = lfb[t];
    for (int i = 0; i < KK; i++) {
        float u = 0.f;
        for (int sp = 0; sp < SPLITN; sp++)
            u += g_pU[((size_t)(b * SPLITN + sp)) * (KK * DD) + i * DD + t];
        sUn[i][t] = fmaf(wt, u / sSv[i], bt);
    }
    __syncthreads();
    float acc[KK];
    #pragma unroll
    for (int i = 0; i < KK; i++) acc[i] = 0.f;
    for (int e = 0; e < DD; e++) {
        float wv = g_WvT[e * DD + t];
        #pragma unroll
        for (int i = 0; i < KK; i++) acc[i] = fmaf(sUn[i][e], wv, acc[i]);
    }
    #pragma unroll
    for (int i = 0; i < KK; i++) g_mid[(b * KK + i) * DD + t] = acc[i];
}

// ------------------------- per-iter: GRU (e-split partials) -------------------------
__global__ void k_gru1() {
    __shared__ float sU[KK][DD];
    __shared__ float sH[KK][DD];
    int b = blockIdx.x, eq = blockIdx.y, t = threadIdx.x;
    for (int r = 0; r < KK; r++) {
        sU[r][t] = g_mid[(b * KK + r) * DD + t];
        sH[r][t] = g_slots[(b * KK + r) * DD + t];
    }
    __syncthreads();
    float air[KK], aiz[KK], ain[KK], ahr[KK], ahz[KK], ahn[KK];
    #pragma unroll
    for (int r = 0; r < KK; r++) { air[r]=aiz[r]=ain[r]=ahr[r]=ahz[r]=ahn[r]=0.f; }
    int e0 = eq * (DD / 4);
    for (int ee = 0; ee < DD / 4; ee++) {
        int e = e0 + ee;
        float wir = g_WihT[e * (3*DD) + t];
        float wiz = g_WihT[e * (3*DD) + DD + t];
        float win = g_WihT[e * (3*DD) + 2*DD + t];
        float whr = g_WhhT[e * (3*DD) + t];
        float whz = g_WhhT[e * (3*DD) + DD + t];
        float whn = g_WhhT[e * (3*DD) + 2*DD + t];
        #pragma unroll
        for (int r = 0; r < KK; r++) {
            float u = sU[r][e], h = sH[r][e];
            air[r] = fmaf(u, wir, air[r]);
            aiz[r] = fmaf(u, wiz, aiz[r]);
            ain[r] = fmaf(u, win, ain[r]);
            ahr[r] = fmaf(h, whr, ahr[r]);
            ahz[r] = fmaf(h, whz, ahz[r]);
            ahn[r] = fmaf(h, whn, ahn[r]);
        }
    }
    float* o = g_pg + ((size_t)(b * 4 + eq) * KK) * (6 * DD);
    for (int r = 0; r < KK; r++) {
        o[r * 6*DD + 0*DD + t] = air[r];
        o[r * 6*DD + 1*DD + t] = aiz[r];
        o[r * 6*DD + 2*DD + t] = ain[r];
        o[r * 6*DD + 3*DD + t] = ahr[r];
        o[r * 6*DD + 4*DD + t] = ahz[r];
        o[r * 6*DD + 5*DD + t] = ahn[r];
    }
}

__global__ void k_gru2(const float* __restrict__ bih, const float* __restrict__ bhh,
                       const float* __restrict__ lpw, const float* __restrict__ lpb) {
    __shared__ float red[32];
    int b = blockIdx.x, t = threadIdx.x;
    for (int r = 0; r < KK; r++) {
        float ir = bih[t], iz = bih[DD + t], in_ = bih[2*DD + t];
        float hr = bhh[t], hz = bhh[DD + t], hn = bhh[2*DD + t];
        for (int eq = 0; eq < 4; eq++) {
            const float* p = g_pg + ((size_t)(b * 4 + eq) * KK + r) * (6 * DD);
            ir += p[t]; iz += p[DD + t]; in_ += p[2*DD + t];
            hr += p[3*DD + t]; hz += p[4*DD + t]; hn += p[5*DD + t];
        }
        float rg = sigm(ir + hr);
        float z  = sigm(iz + hz);
        float n  = tanhf(fmaf(rg, hn, in_));
        float hprev = g_slots[(b * KK + r) * DD + t];
        float hy = fmaf(z, hprev - n, n);
        float m  = blockSum(hy, red) * (1.f / DD);
        float d  = hy - m;
        float var = blockSum(d * d, red) * (1.f / DD);
        float lnp = d * rsqrtf(var + LN_EPSF) * lpw[t] + lpb[t];
        g_slots[(b * KK + r) * DD + t] = hy;
        g_mid  [(b * KK + r) * DD + t] = lnp;
    }
}

// ------------------------- per-iter: MLP -------------------------
__global__ void k_mlp1(const float* __restrict__ b1) {
    __shared__ float sP[KK][DD];
    int b = blockIdx.x, q = blockIdx.y, t = threadIdx.x;
    int h = q * DD + t;
    for (int r = 0; r < KK; r++) sP[r][t] = g_mid[(b * KK + r) * DD + t];
    __syncthreads();
    float acc[KK];
    #pragma unroll
    for (int r = 0; r < KK; r++) acc[r] = 0.f;
    for (int e = 0; e < DD; e++) {
        float wv = g_W1T[e * HH + h];
        #pragma unroll
        for (int r = 0; r < KK; r++) acc[r] = fmaf(sP[r][e], wv, acc[r]);
    }
    float bb = b1[h];
    #pragma unroll
    for (int r = 0; r < KK; r++)
        g_h1[(b * KK + r) * HH + h] = fmaxf(acc[r] + bb, 0.f);
}

__global__ void k_mlp2() {
    __shared__ float sh1[KK][DD];
    int b = blockIdx.x, eh = blockIdx.y, t = threadIdx.x;
    for (int r = 0; r < KK; r++) sh1[r][t] = g_h1[(b * KK + r) * HH + eh * DD + t];
    __syncthreads();
    float acc[KK];
    #pragma unroll
    for (int r = 0; r < KK; r++) acc[r] = 0.f;
    for (int e = 0; e < DD; e++) {
        float wv = g_W2T[(eh * DD + e) * DD + t];
        #pragma unroll
        for (int r = 0; r < KK; r++) acc[r] = fmaf(sh1[r][e], wv, acc[r]);
    }
    #pragma unroll
    for (int r = 0; r < KK; r++)
        g_pm[((size_t)(b * 2 + eh) * KK + r) * DD + t] = acc[r];
}

__global__ void k_mlp2b(const float* __restrict__ b2, float* __restrict__ outp) {
    int b = blockIdx.x, t = threadIdx.x;
    float bt = b2[t];
    for (int r = 0; r < KK; r++) {
        int idx = (b * KK + r) * DD + t;
        float v = g_slots[idx]
                + g_pm[((size_t)(b * 2 + 0) * KK + r) * DD + t]
                + g_pm[((size_t)(b * 2 + 1) * KK + r) * DD + t]
                + bt;
        g_slots[idx] = v;
        outp[idx] = v;
    }
}

// ------------------------- launch -------------------------
extern "C" void kernel_launch(void* const* d_in, const int* in_sizes, int n_in,
                              void* d_out, int out_size) {
    const float* inputs = (const float*)d_in[0];
    const float* slots0 = (const float*)d_in[1];
    const float* ln_f_w = (const float*)d_in[2];
    const float* ln_f_b = (const float*)d_in[3];
    const float* ln_s_w = (const float*)d_in[4];
    const float* ln_s_b = (const float*)d_in[5];
    const float* ln_p_w = (const float*)d_in[6];
    const float* ln_p_b = (const float*)d_in[7];
    const float* Wq  = (const float*)d_in[8];
    const float* Wk  = (const float*)d_in[9];
    const float* Wv  = (const float*)d_in[10];
    const float* Wih = (const float*)d_in[11];
    const float* bih = (const float*)d_in[12];
    const float* Whh = (const float*)d_in[13];
    const float* bhh = (const float*)d_in[14];
    const float* W1  = (const float*)d_in[15];
    const float* b1  = (const float*)d_in[16];
    const float* W2  = (const float*)d_in[17];
    const float* b2  = (const float*)d_in[18];
    float* outp = (float*)d_out;

    // launch indices: 0 transAll, 1 mqk, 2 copy, 3 xhat, 4 qgen, 5 attn  (ncu -s 5 hits k_attn)
    k_transAll<<<704, dim3(32, 8)>>>(Wv, Wih, Whh, W1, W2);
    k_mqk<<<DD, DD>>>(Wq, Wk);
    k_copy_slots<<<(SLOTSZ + 255) / 256, 256>>>(slots0);
    k_xhat<<<(BB * NN) / 8, 256>>>(inputs);

    for (int it = 0; it < NITER; it++) {
        k_qgen<<<BB, DD>>>(ln_s_w, ln_s_b, ln_f_w, ln_f_b);
        k_attn<<<dim3(BB, SPLITN), 128>>>();
        k_comb<<<BB, DD>>>(ln_f_w, ln_f_b);
        k_gru1<<<dim3(BB, 4), DD>>>();
        k_gru2<<<BB, DD>>>(bih, bhh, ln_p_w, ln_p_b);
        k_mlp1<<<dim3(BB, 2), DD>>>(b1);
        k_mlp2<<<dim3(BB, 2), DD>>>();
        k_mlp2b<<<BB, DD>>>(b2, outp);
    }
}